// round 16
// baseline (speedup 1.0000x reference)
#include <cuda_runtime.h>

#define BB 512      // batch rows
#define NT 1024     // threads per block
#define NWB 16      // warps holding rows (512/32)
#define NW2 32      // warps per block
#define LL 100      // labels
#define DLEN 100000
#define GAMMA 0.9f

__device__ float g_per_label[LL];
__device__ unsigned int g_cnt = 0;

// Packed f32x2 sweep over the SORTED array: positive prefix [0, np4) feeds
// S_pos; negative suffix [np4, np4+na4) feeds the remainder of S_all.
// Each thread takes the 1/K interleaved slice of both ranges.
template<int K>
__device__ __forceinline__ void compute_sums_sorted(
    const ulonglong2* __restrict__ srt2, int np4, int na4,
    unsigned long long c2, int sub, float& S_all, float& S_pos)
{
    // positive prefix
    unsigned long long p0 = 0ull, p1 = 0ull;
    const int hp = np4 / K;             // np4 is a multiple of K
#pragma unroll 4
    for (int jj = 0; jj < hp; jj++) {
        ulonglong2 v = srt2[K * jj + sub];
        asm("{\n\t"
            ".reg .b64 e0, e1;\n\t"
            ".reg .f32 x0, x1, x2, x3;\n\t"
            "add.rn.f32x2 e0, %2, %4;\n\t"
            "add.rn.f32x2 e1, %3, %4;\n\t"
            "mov.b64 {x0, x1}, e0;\n\t"
            "mov.b64 {x2, x3}, e1;\n\t"
            "max.f32 x0, x0, 0f00000000;\n\t"
            "max.f32 x1, x1, 0f00000000;\n\t"
            "max.f32 x2, x2, 0f00000000;\n\t"
            "max.f32 x3, x3, 0f00000000;\n\t"
            "mov.b64 e0, {x0, x1};\n\t"
            "mov.b64 e1, {x2, x3};\n\t"
            "fma.rn.f32x2 %0, e0, e0, %0;\n\t"
            "fma.rn.f32x2 %1, e1, e1, %1;\n\t"
            "}" : "+l"(p0), "+l"(p1) : "l"(v.x), "l"(v.y), "l"(c2));
    }
    float pl0, ph0, pl1, ph1;
    asm("mov.b64 {%0, %1}, %2;" : "=f"(pl0), "=f"(ph0) : "l"(p0));
    asm("mov.b64 {%0, %1}, %2;" : "=f"(pl1), "=f"(ph1) : "l"(p1));
    S_pos = (pl0 + ph0) + (pl1 + ph1);

    // negative suffix
    unsigned long long a0 = 0ull, a1 = 0ull;
    const int ha = na4 / K;
#pragma unroll 4
    for (int jj = 0; jj < ha; jj++) {
        ulonglong2 v = srt2[np4 + K * jj + sub];
        asm("{\n\t"
            ".reg .b64 e0, e1;\n\t"
            ".reg .f32 x0, x1, x2, x3;\n\t"
            "add.rn.f32x2 e0, %2, %4;\n\t"
            "add.rn.f32x2 e1, %3, %4;\n\t"
            "mov.b64 {x0, x1}, e0;\n\t"
            "mov.b64 {x2, x3}, e1;\n\t"
            "max.f32 x0, x0, 0f00000000;\n\t"
            "max.f32 x1, x1, 0f00000000;\n\t"
            "max.f32 x2, x2, 0f00000000;\n\t"
            "max.f32 x3, x3, 0f00000000;\n\t"
            "mov.b64 e0, {x0, x1};\n\t"
            "mov.b64 e1, {x2, x3};\n\t"
            "fma.rn.f32x2 %0, e0, e0, %0;\n\t"
            "fma.rn.f32x2 %1, e1, e1, %1;\n\t"
            "}" : "+l"(a0), "+l"(a1) : "l"(v.x), "l"(v.y), "l"(c2));
    }
    float al0, ah0, al1, ah1;
    asm("mov.b64 {%0, %1}, %2;" : "=f"(al0), "=f"(ah0) : "l"(a0));
    asm("mov.b64 {%0, %1}, %2;" : "=f"(al1), "=f"(ah1) : "l"(a1));
    S_all = S_pos + ((al0 + ah0) + (al1 + ah1));
}

__global__ __launch_bounds__(NT, 1) void map_loss_fused_kernel(
    const float* __restrict__ y_pred,   // (B, L)
    const float* __restrict__ y_true,   // (B, L)
    const int*   __restrict__ index,    // (B,)
    const float* __restrict__ u_all,    // (L, DLEN)
    const float* __restrict__ u_pos,    // (L, DLEN)
    float* __restrict__ out)
{
    // sorted fp: positives (padded to <=32 extra), then negatives (padded).
    __shared__ __align__(16) float s_srt[BB + 64];
    __shared__ float s_Sa[BB];          // per-slot S_all
    __shared__ float s_Sp[BB];          // per-slot S_pos
    __shared__ int   s_wcnt[NWB];
    __shared__ float s_wsum[NW2];

    const int l    = blockIdx.x;
    const int t    = threadIdx.x;
    const int warp = t >> 5;
    const int lane = t & 31;
    const bool row_thr = t < BB;        // warp-uniform (warps 0..15)

    // ---- row threads issue ALL independent global loads immediately ----
    int   idx = 0; float fp_i = 0.f, yt = 0.f, ua_v = 1.f, up_v = 1.f;
    bool  pos_i = false;
    unsigned m = 0;
    if (row_thr) {
        idx  = index[t];
        fp_i = y_pred[t * LL + l];
        yt   = y_true[t * LL + l];
        ua_v = u_all[(long long)l * DLEN + idx];   // stay in regs
        up_v = u_pos[(long long)l * DLEN + idx];
        pos_i = (yt == 1.0f);
        m = __ballot_sync(0xffffffffu, pos_i);
        if (lane == 0) s_wcnt[warp] = __popc(m);
    }
    if (t < BB + 64) s_srt[t] = -1e30f;            // pad -> relu = 0
    __syncthreads();                                            // bar1

    // ---- prefix over warp counts; block-uniform n_pos ----
    int base = 0, total = 0;
#pragma unroll
    for (int w = 0; w < NWB; w++) {
        int cc = s_wcnt[w];
        if (w < warp) base += cc;
        total += cc;
    }
    const int n_pos = total;                       // >= 1

    // ---- K selection (block-uniform); padding matches K ----
    int n_act_thr, Ksel, pad;
    if (8 * n_pos <= NT)      { Ksel = 8; n_act_thr = 8 * n_pos; pad = 32; }
    else if (4 * n_pos <= NT) { Ksel = 4; n_act_thr = 4 * n_pos; pad = 16; }
    else                      { Ksel = 2; n_act_thr = 2 * n_pos; pad = 8;  }

    const int n_pos_pad = (n_pos + pad - 1) & ~(pad - 1);
    const int np4       = n_pos_pad >> 2;          // multiple of K
    const int n_neg     = BB - n_pos;
    const int na4       = ((n_neg + pad - 1) & ~(pad - 1)) >> 2;

    // ---- deterministic 2-way compaction (row threads only) ----
    int my_slot = -1;
    if (row_thr) {
        const int lane_pos = __popc(m & ((1u << lane) - 1u));
        if (pos_i) {
            my_slot = base + lane_pos;
            s_srt[my_slot] = fp_i;
        } else {
            const int noff = (32 * warp - base) + (lane - lane_pos);
            s_srt[n_pos_pad + noff] = fp_i;
        }
    }
    __syncthreads();                                            // bar2

    const int n_act_wrp = (n_act_thr + 31) >> 5;

    if (warp < n_act_wrp) {             // warp-uniform; idle warps skip
        const bool act = t < n_act_thr;
        const ulonglong2* srt2 = reinterpret_cast<const ulonglong2*>(s_srt);

        int slot, sub;
        float S_all = 0.f, S_pos = 0.f;
        if (Ksel == 8)      { slot = t >> 3; sub = t & 7; }
        else if (Ksel == 4) { slot = t >> 2; sub = t & 3; }
        else                { slot = t >> 1; sub = t & 1; }

        const float cs = act ? (1.0f - s_srt[slot]) : -1e30f;
        unsigned long long c2;
        asm("mov.b64 %0, {%1, %1};" : "=l"(c2) : "f"(cs));

        if (Ksel == 8) {
            compute_sums_sorted<8>(srt2, np4, na4, c2, sub, S_all, S_pos);
            S_all += __shfl_xor_sync(0xffffffffu, S_all, 1);
            S_all += __shfl_xor_sync(0xffffffffu, S_all, 2);
            S_all += __shfl_xor_sync(0xffffffffu, S_all, 4);
            S_pos += __shfl_xor_sync(0xffffffffu, S_pos, 1);
            S_pos += __shfl_xor_sync(0xffffffffu, S_pos, 2);
            S_pos += __shfl_xor_sync(0xffffffffu, S_pos, 4);
        } else if (Ksel == 4) {
            compute_sums_sorted<4>(srt2, np4, na4, c2, sub, S_all, S_pos);
            S_all += __shfl_xor_sync(0xffffffffu, S_all, 1);
            S_all += __shfl_xor_sync(0xffffffffu, S_all, 2);
            S_pos += __shfl_xor_sync(0xffffffffu, S_pos, 1);
            S_pos += __shfl_xor_sync(0xffffffffu, S_pos, 2);
        } else {
            compute_sums_sorted<2>(srt2, np4, na4, c2, sub, S_all, S_pos);
            S_all += __shfl_xor_sync(0xffffffffu, S_all, 1);
            S_pos += __shfl_xor_sync(0xffffffffu, S_pos, 1);
        }

        if (act && sub == 0) {          // publish per-slot sums
            s_Sa[slot] = S_all;
            s_Sp[slot] = S_pos;
        }
    }
    __syncthreads();                                            // bar3

    // ---- each POSITIVE row thread computes its own contribution ----
    float contrib = 0.0f;
    if (pos_i) {                        // implies row_thr
        const float Sa = s_Sa[my_slot];
        const float Sp = s_Sp[my_slot];
        const float ua_new = (1.0f - GAMMA) * ua_v + GAMMA * (Sa * (1.0f / (float)BB));
        const float up_new = (1.0f - GAMMA) * up_v + GAMMA * (Sp * (1.0f / (float)BB));
        contrib = (up_new * Sa - ua_new * Sp) / (ua_new * ua_new);
    }

    // ---- block reduction: warp shuffle + cross-warp fold (deterministic) ----
    float v = contrib;
#pragma unroll
    for (int off = 16; off > 0; off >>= 1)
        v += __shfl_down_sync(0xffffffffu, v, off);
    if (lane == 0) s_wsum[warp] = v;
    __syncthreads();                                            // bar4 (last)

    if (warp == 0) {
        float v2 = s_wsum[lane];        // NW2 == 32 — exact fit
#pragma unroll
        for (int off = 16; off > 0; off >>= 1)
            v2 += __shfl_down_sync(0xffffffffu, v2, off);

        unsigned old = 0;
        if (lane == 0) {
            g_per_label[l] = v2 / ((float)n_pos * (float)BB);
            // acq_rel RMW: release orders the store above; acquire orders
            // the last block's fold loads. No MEMBAR.GPU pair needed.
            unsigned* cnt_ptr = &g_cnt;
            asm volatile("atom.acq_rel.gpu.global.add.u32 %0, [%1], %2;"
                         : "=r"(old) : "l"(cnt_ptr), "r"(1u) : "memory");
        }
        old = __shfl_sync(0xffffffffu, old, 0);    // warp broadcast

        if (old == LL - 1) {                        // last block: fold 100 values
            volatile float* gp = g_per_label;
            float a = 0.0f;
#pragma unroll
            for (int j = 0; j < 4; j++) {
                const int i2 = lane + j * 32;
                if (i2 < LL) a += gp[i2];
            }
#pragma unroll
            for (int off = 16; off > 0; off >>= 1)
                a += __shfl_down_sync(0xffffffffu, a, off);
            if (lane == 0) {
                out[0] = a / (float)LL;
                g_cnt = 0;                          // reset for next replay
            }
        }
    }
}

extern "C" void kernel_launch(void* const* d_in, const int* in_sizes, int n_in,
                              void* d_out, int out_size) {
    const float* y_pred = (const float*)d_in[0];
    const float* y_true = (const float*)d_in[1];
    const int*   index  = (const int*)d_in[2];
    const float* u_all  = (const float*)d_in[3];
    const float* u_pos  = (const float*)d_in[4];
    float* out = (float*)d_out;

    map_loss_fused_kernel<<<LL, NT>>>(y_pred, y_true, index, u_all, u_pos, out);
}